// round 17
// baseline (speedup 1.0000x reference)
#include <cuda_runtime.h>
#include <cuda_bf16.h>
#include <math.h>

// Problem dims
#define Hn 512
#define Dn 128
#define Nn 64
#define Tn 512

// K3: 16 clusters x 8 CTAs; cluster = 4 seqs as TWO chains of 2.
#define K3_CL 8
#define ROWF  544                  // floats per s-row: 8 chunks x (64+4 pad)
#define ROW_B 2176u                // ROWF*4
#define CP_B  4352u                // per (chain,phase) block: 2 s-rows
#define CH_B  8704u                // per chain: 2 phases
// per chain-phase incoming: alpha 8src*512B + ps 8src*64B
#define RX_CHAIN 4608u

// ---------------- device scratch (static globals: no allocation) -------------
__device__ float g_E[(size_t)Tn * Nn * Hn];   // exp(emit - m); [t][n][h]
__device__ float g_M[Tn * Nn];                // rowmax m[t][n]
__device__ float g_Wt[Dn * Hn];
__device__ float g_bias[Hn];

// ---------------- helpers -----------------------------------------------------
__device__ __forceinline__ unsigned long long ffma2(unsigned long long a,
                                                    unsigned long long b,
                                                    unsigned long long c) {
    unsigned long long d;
    asm("fma.rn.f32x2 %0, %1, %2, %3;" : "=l"(d) : "l"(a), "l"(b), "l"(c));
    return d;
}
__device__ __forceinline__ unsigned long long fadd2(unsigned long long a,
                                                    unsigned long long b) {
    unsigned long long d;
    asm("add.rn.f32x2 %0, %1, %2;" : "=l"(d) : "l"(a), "l"(b));
    return d;
}
__device__ __forceinline__ unsigned long long fmul2(unsigned long long a,
                                                    unsigned long long b) {
    unsigned long long d;
    asm("mul.rn.f32x2 %0, %1, %2;" : "=l"(d) : "l"(a), "l"(b));
    return d;
}
__device__ __forceinline__ float2 up2(unsigned long long v) {
    float2 r;
    asm("mov.b64 {%0, %1}, %2;" : "=f"(r.x), "=f"(r.y) : "l"(v));
    return r;
}
__device__ __forceinline__ unsigned long long pack2(float lo, float hi) {
    unsigned long long v;
    asm("mov.b64 %0, {%1, %2};" : "=l"(v) : "f"(lo), "f"(hi));
    return v;
}
__device__ __forceinline__ unsigned smem_u32(const void* p) {
    return (unsigned)__cvta_generic_to_shared(p);
}
__device__ __forceinline__ unsigned mapa_rank(unsigned saddr, unsigned rank) {
    unsigned r;
    asm("mapa.shared::cluster.u32 %0, %1, %2;" : "=r"(r) : "r"(saddr), "r"(rank));
    return r;
}
__device__ __forceinline__ void st_async_b64_pre(unsigned raddr, unsigned rmbar,
                                                 unsigned long long v) {
    asm volatile(
        "st.async.shared::cluster.mbarrier::complete_tx::bytes.b64 [%0], %1, [%2];"
        :: "r"(raddr), "l"(v), "r"(rmbar) : "memory");
}
__device__ __forceinline__ void mbar_init(unsigned mbar, unsigned count) {
    asm volatile("mbarrier.init.shared.b64 [%0], %1;" :: "r"(mbar), "r"(count) : "memory");
}
__device__ __forceinline__ void mbar_expect(unsigned mbar, unsigned bytes) {
    asm volatile("mbarrier.arrive.expect_tx.shared.b64 _, [%0], %1;"
                 :: "r"(mbar), "r"(bytes) : "memory");
}
__device__ __forceinline__ void mbar_wait(unsigned mbar, unsigned parity) {
    asm volatile(
        "{\n\t.reg .pred P1;\n\t"
        "WL_%=:\n\t"
        "mbarrier.try_wait.parity.acquire.cta.shared::cta.b64 P1, [%0], %1, 0x989680;\n\t"
        "@P1 bra.uni WD_%=;\n\t"
        "bra.uni WL_%=;\n\t"
        "WD_%=:\n\t}"
        :: "r"(mbar), "r"(parity) : "memory");
}
__device__ __forceinline__ void cluster_sync_hw() {
    asm volatile("barrier.cluster.arrive.aligned;" ::: "memory");
    asm volatile("barrier.cluster.wait.aligned;" ::: "memory");
}

// ---------------- K0: W^T and bias ------------------------------------------
__global__ void hmm_k0(const float* __restrict__ py) {
    int h = blockIdx.x * 8 + (threadIdx.x >> 5);
    int lane = threadIdx.x & 31;
    float s = 0.f;
#pragma unroll
    for (int c = 0; c < 4; c++) {
        int d = lane + c * 32;
        float p = __ldg(py + (size_t)h * Dn + d);
        float l1 = log1pf(-p);
        g_Wt[(size_t)d * Hn + h] = logf(p) - l1;
        s += l1;
    }
#pragma unroll
    for (int o = 16; o; o >>= 1) s += __shfl_xor_sync(0xffffffffu, s, o);
    if (lane == 0) g_bias[h] = s;
}

// ---------------- K1: emission GEMM ------------------------------------------
#define K1_SMEM ((64 * 132 + 128 * 128) * 4)
__global__ void __launch_bounds__(256) hmm_k1(const float* __restrict__ seq) {
    extern __shared__ float sm1[];
    float* seq_s = sm1;
    float* W_s   = sm1 + 64 * 132;

    int tid = threadIdx.x;
    int tb = blockIdx.y;
    int h0 = blockIdx.x * 128;

    for (int idx = tid; idx < 64 * 32; idx += 256) {
        int n = idx >> 5, d4 = idx & 31;
        float4 v = __ldg((const float4*)(seq + ((size_t)n * Tn + tb) * Dn + d4 * 4));
        *(float4*)&seq_s[n * 132 + d4 * 4] = v;
    }
    for (int idx = tid; idx < 128 * 32; idx += 256) {
        int k = idx >> 5, h4 = idx & 31;
        float4 v = __ldg((const float4*)(g_Wt + (size_t)k * Hn + h0 + h4 * 4));
        *(float4*)&W_s[k * 128 + h4 * 4] = v;
    }
    __syncthreads();

    int tx = tid & 15;
    int ty = tid >> 4;
    float acc[4][8];
#pragma unroll
    for (int u = 0; u < 4; u++)
#pragma unroll
        for (int v = 0; v < 8; v++) acc[u][v] = 0.f;

#pragma unroll 4
    for (int k = 0; k < 128; k++) {
        float aa[4];
#pragma unroll
        for (int u = 0; u < 4; u++) aa[u] = seq_s[(ty * 4 + u) * 132 + k];
        float4 b0 = *(const float4*)&W_s[k * 128 + tx * 8];
        float4 b1 = *(const float4*)&W_s[k * 128 + tx * 8 + 4];
        float bb[8] = {b0.x, b0.y, b0.z, b0.w, b1.x, b1.y, b1.z, b1.w};
#pragma unroll
        for (int u = 0; u < 4; u++)
#pragma unroll
            for (int v = 0; v < 8; v++) acc[u][v] = fmaf(aa[u], bb[v], acc[u][v]);
    }

    float4 bi0 = *(const float4*)&g_bias[h0 + tx * 8];
    float4 bi1 = *(const float4*)&g_bias[h0 + tx * 8 + 4];
    float bb[8] = {bi0.x, bi0.y, bi0.z, bi0.w, bi1.x, bi1.y, bi1.z, bi1.w};
#pragma unroll
    for (int u = 0; u < 4; u++) {
        size_t r = (size_t)tb * 64 + ty * 4 + u;
        float4 o0 = make_float4(acc[u][0] + bb[0], acc[u][1] + bb[1],
                                acc[u][2] + bb[2], acc[u][3] + bb[3]);
        float4 o1 = make_float4(acc[u][4] + bb[4], acc[u][5] + bb[5],
                                acc[u][6] + bb[6], acc[u][7] + bb[7]);
        *(float4*)&g_E[r * Hn + h0 + tx * 8]     = o0;
        *(float4*)&g_E[r * Hn + h0 + tx * 8 + 4] = o1;
    }
}

// ---------------- K2: rowmax + exp(emit - m) ---------------------------------
__global__ void __launch_bounds__(256) hmm_k2() {
    int r = blockIdx.x * 8 + (threadIdx.x >> 5);
    int lane = threadIdx.x & 31;
    float* row = g_E + (size_t)r * Hn;
    float4 v[4];
    float m = -3.0e38f;
#pragma unroll
    for (int c = 0; c < 4; c++) {
        v[c] = *(const float4*)(row + c * 128 + lane * 4);
        m = fmaxf(m, fmaxf(fmaxf(v[c].x, v[c].y), fmaxf(v[c].z, v[c].w)));
    }
#pragma unroll
    for (int o = 16; o; o >>= 1) m = fmaxf(m, __shfl_xor_sync(0xffffffffu, m, o));
#pragma unroll
    for (int c = 0; c < 4; c++) {
        float4 e = make_float4(__expf(v[c].x - m), __expf(v[c].y - m),
                               __expf(v[c].z - m), __expf(v[c].w - m));
        *(float4*)(row + c * 128 + lane * 4) = e;
    }
    if (lane == 0) g_M[r] = m;
}

// ---------------- K3: sync-free dual-chain cluster recursion -----------------
// Thread (w, lane): jp = lane>>3 (j-pair within warp), ic = lane&7 (64-i chunk).
// j-pair global: rank*64 + w*8 + 2*jp. P regs: 64 i x 2 j = 64 ull.
__global__ void __launch_bounds__(256, 1) __cluster_dims__(K3_CL, 1, 1)
hmm_k3(const float* __restrict__ px, const int* __restrict__ lengths,
       float* __restrict__ out) {
    __shared__ alignas(16) float buf[2][2][2][ROWF];          // [c][p][s][row]
    __shared__ alignas(16) unsigned long long psb[2][2][8][8]; // [c][p][src][w]
    __shared__ unsigned long long mbar[2][2];                  // [c][p]
    __shared__ int len_sm[4];

    const int tid  = threadIdx.x;
    const int w    = tid >> 5;
    const int lane = tid & 31;
    const int jp   = lane >> 3;
    const int ic   = lane & 7;
    unsigned rank;
    asm("mov.u32 %0, %%cluster_ctarank;" : "=r"(rank));
    const int grp = blockIdx.x >> 3;
    const int n0  = grp * 4;

    const int jg0   = (int)rank * 64 + w * 8 + jp * 2;  // my dot j-pair (global)
    const int i0    = ic * 64;                          // my i-chunk base

    // P -> registers: Pp[j][m] = pack(P[i0+2m][jg0+j], P[i0+2m+1][jg0+j])
    unsigned long long Pp[2][32];
#pragma unroll
    for (int m = 0; m < 32; m++) {
        const float* r0 = px + (size_t)(i0 + 2 * m) * Hn;
        const float* r1 = px + (size_t)(i0 + 2 * m + 1) * Hn;
        Pp[0][m] = pack2(__ldg(r0 + jg0),     __ldg(r1 + jg0));
        Pp[1][m] = pack2(__ldg(r0 + jg0 + 1), __ldg(r1 + jg0 + 1));
    }
    if (tid < 4) {
        mbar_init(smem_u32(&mbar[tid >> 1][tid & 1]), 1);
        len_sm[tid] = __ldg(lengths + n0 + tid);
    }
    __syncthreads();
    if (tid < 4) mbar_expect(smem_u32(&mbar[tid >> 1][tid & 1]), RX_CHAIN);
    int len4[4];
#pragma unroll
    for (int i = 0; i < 4; i++) len4[i] = len_sm[i];
    cluster_sync_hw();                                   // inits visible

    // hoisted remote bases
    const unsigned base_l = smem_u32(&buf[0][0][0][0]);
    unsigned ra_base[K3_CL];
#pragma unroll
    for (unsigned i = 0; i < K3_CL; i++)
        ra_base[i] = mapa_rank(base_l, (rank + i) & 7u);
    // pusher deltas (lanes 0..7): s_p = ℓ>>2, jp_src = ℓ&3
    const int s_p   = (lane >> 2) & 1;
    const int jp_s  = lane & 3;
    const int jgp   = (int)rank * 64 + w * 8 + 2 * jp_s; // pushed pair dest-i idx
    const unsigned d_alpha0 = (unsigned)(s_p * ROW_B)
        + 4u * (unsigned)((jgp >> 6) * 68 + (jgp & 63)); // within (c,p) block
    const unsigned d_mbar0  = smem_u32(&mbar[0][0]) - base_l;
    const unsigned d_ps0    = smem_u32(&psb[0][0][rank][w]) - base_l;

    const bool book = (rank == 0 && w == 0 && lane == 0);
    float C0 = 0.f, C1 = 0.f, C2 = 0.f, C3 = 0.f;
    if (book) {
        float4 m0 = __ldg((const float4*)(g_M + n0));
        C0 = m0.x; C1 = m0.y; C2 = m0.z; C3 = m0.w;
    }

    // ---- t = 0: acc2[c][s] for my jp; push both chains (phase 0) ----
    unsigned long long acc2[2][2];
    {
        const int jgm = (int)rank * 64 + w * 8 + 2 * jp;
        float p0 = __ldg(px + jgm), p1 = __ldg(px + jgm + 1);
#pragma unroll
        for (int c = 0; c < 2; c++)
#pragma unroll
            for (int s = 0; s < 2; s++) {
                float2 e0 = __ldcg((const float2*)(g_E +
                            (size_t)(n0 + 2 * c + s) * Hn + jgm));
                acc2[c][s] = pack2(p0 * e0.x, p1 * e0.y);
            }
    }
    // push helper pattern (expanded twice per use-site below)
#define PUSH_CHAIN(cc, pp)                                                      \
    do {                                                                        \
        unsigned long long v0 = __shfl_sync(0xffffffffu, acc2[cc][0], jp_s * 8);\
        unsigned long long v1 = __shfl_sync(0xffffffffu, acc2[cc][1], jp_s * 8);\
        unsigned long long vv = s_p ? v1 : v0;                                  \
        unsigned da = d_alpha0 + (cc) * CH_B + (pp) * CP_B;                     \
        unsigned dm = d_mbar0 + (unsigned)((cc) * 16 + (pp) * 8);               \
        if (lane < 8) {                                                         \
            _Pragma("unroll")                                                   \
            for (unsigned i = 0; i < K3_CL; i++)                                \
                st_async_b64_pre(ra_base[i] + da, ra_base[i] + dm, vv);         \
        }                                                                       \
        unsigned long long sv0 = acc2[cc][0], sv1 = acc2[cc][1];                \
        sv0 = fadd2(sv0, __shfl_xor_sync(0xffffffffu, sv0, 8));                 \
        sv0 = fadd2(sv0, __shfl_xor_sync(0xffffffffu, sv0, 16));                \
        sv1 = fadd2(sv1, __shfl_xor_sync(0xffffffffu, sv1, 8));                 \
        sv1 = fadd2(sv1, __shfl_xor_sync(0xffffffffu, sv1, 16));                \
        if (lane == 0) {                                                        \
            float2 f0 = up2(sv0), f1 = up2(sv1);                                \
            unsigned long long psv = pack2(f0.x + f0.y, f1.x + f1.y);           \
            unsigned dp = d_ps0 + (unsigned)(((cc) * 2 + (pp)) * 512);          \
            unsigned dm2 = d_mbar0 + (unsigned)((cc) * 16 + (pp) * 8);          \
            _Pragma("unroll")                                                   \
            for (unsigned i = 0; i < K3_CL; i++)                                \
                st_async_b64_pre(ra_base[i] + dp, ra_base[i] + dm2, psv);       \
        }                                                                       \
    } while (0)

    PUSH_CHAIN(0, 0);
    PUSH_CHAIN(1, 0);

    for (int t = 1; t < Tn; t++) {
        const int rp = (t - 1) & 1;
        const int pb = t & 1;
        const unsigned parity = (unsigned)(((t - 1) >> 1) & 1);

        // prefetches
        unsigned long long e2[2][2];
#pragma unroll
        for (int c = 0; c < 2; c++)
#pragma unroll
            for (int s = 0; s < 2; s++) {
                float2 ee = __ldcg((const float2*)(g_E +
                    ((size_t)t * Nn + n0 + 2 * c + s) * Hn + jg0));
                e2[c][s] = pack2(ee.x, ee.y);
            }
        float4 m4 = make_float4(0.f, 0.f, 0.f, 0.f);
        if (book) m4 = __ldg((const float4*)(g_M + (size_t)t * Nn + n0));

#pragma unroll
        for (int c = 0; c < 2; c++) {
            const unsigned mb = smem_u32(&mbar[c][rp]);
            mbar_wait(mb, parity);
            if (w == 0 && lane == 0) mbar_expect(mb, RX_CHAIN);

            // R from ps butterfly (all lanes get S as f32x2)
            unsigned long long s2;
            {
                const ulonglong2* pv = (const ulonglong2*)&psb[c][rp][0][0];
                ulonglong2 a = pv[lane & 15];
                s2 = fadd2(a.x, a.y);
                s2 = fadd2(s2, __shfl_xor_sync(0xffffffffu, s2, 1));
                s2 = fadd2(s2, __shfl_xor_sync(0xffffffffu, s2, 2));
                s2 = fadd2(s2, __shfl_xor_sync(0xffffffffu, s2, 4));
                s2 = fadd2(s2, __shfl_xor_sync(0xffffffffu, s2, 8));
            }
            float2 Sf = up2(s2);
            float R0 = __fdividef(1.0f, Sf.x);
            float R1 = __fdividef(1.0f, Sf.y);
            if (book) {
                float mm0 = c ? m4.z : m4.x;
                float mm1 = c ? m4.w : m4.y;
                if (c == 0) {
                    if (t < len4[0]) C0 += __logf(Sf.x) + mm0;
                    if (t < len4[1]) C1 += __logf(Sf.y) + mm1;
                } else {
                    if (t < len4[2]) C2 += __logf(Sf.x) + mm0;
                    if (t < len4[3]) C3 += __logf(Sf.y) + mm1;
                }
            }

            // dot: 2 s x (16 LDS.128 + 64 FFMA2) over my 64-i chunk, 2 j
            unsigned long long q00 = 0ull, q01 = 0ull, q10 = 0ull, q11 = 0ull;
            {
                const ulonglong2* a0 = (const ulonglong2*)&buf[c][rp][0][ic * 68];
                const ulonglong2* a1 = (const ulonglong2*)&buf[c][rp][1][ic * 68];
#pragma unroll
                for (int k = 0; k < 16; k++) {
                    ulonglong2 v0 = a0[k];
                    q00 = ffma2(v0.x, Pp[0][2 * k],     q00);
                    q00 = ffma2(v0.y, Pp[0][2 * k + 1], q00);
                    q01 = ffma2(v0.x, Pp[1][2 * k],     q01);
                    q01 = ffma2(v0.y, Pp[1][2 * k + 1], q01);
                    ulonglong2 v1 = a1[k];
                    q10 = ffma2(v1.x, Pp[0][2 * k],     q10);
                    q10 = ffma2(v1.y, Pp[0][2 * k + 1], q10);
                    q11 = ffma2(v1.x, Pp[1][2 * k],     q11);
                    q11 = ffma2(v1.y, Pp[1][2 * k + 1], q11);
                }
            }
            // horizontal: tot2[s] = (j0_sum, j1_sum), then butterfly over ic
            float2 f00 = up2(q00), f01 = up2(q01), f10 = up2(q10), f11 = up2(q11);
            unsigned long long tot0 = pack2(f00.x + f00.y, f01.x + f01.y);
            unsigned long long tot1 = pack2(f10.x + f10.y, f11.x + f11.y);
            tot0 = fadd2(tot0, __shfl_xor_sync(0xffffffffu, tot0, 1));
            tot0 = fadd2(tot0, __shfl_xor_sync(0xffffffffu, tot0, 2));
            tot0 = fadd2(tot0, __shfl_xor_sync(0xffffffffu, tot0, 4));
            tot1 = fadd2(tot1, __shfl_xor_sync(0xffffffffu, tot1, 1));
            tot1 = fadd2(tot1, __shfl_xor_sync(0xffffffffu, tot1, 2));
            tot1 = fadd2(tot1, __shfl_xor_sync(0xffffffffu, tot1, 4));

            unsigned long long n0v = fmul2(fmul2(tot0, pack2(R0, R0)), e2[c][0]);
            unsigned long long n1v = fmul2(fmul2(tot1, pack2(R1, R1)), e2[c][1]);
            if (t < len4[2 * c + 0]) acc2[c][0] = n0v;
            if (t < len4[2 * c + 1]) acc2[c][1] = n1v;

            if (c == 0) PUSH_CHAIN(0, pb); else PUSH_CHAIN(1, pb);
        }
    }

    // drain final phase (t=511 pushes, phase 1, parity 1) for both chains
    mbar_wait(smem_u32(&mbar[0][1]), 1u);
    mbar_wait(smem_u32(&mbar[1][1]), 1u);

    // output: rank0 warp0 (warp-collective butterflies, lane0 writes)
    if (rank == 0 && w == 0) {
        float Cv[4] = {C0, C1, C2, C3};
#pragma unroll
        for (int c = 0; c < 2; c++) {
            const ulonglong2* pv = (const ulonglong2*)&psb[c][1][0][0];
            ulonglong2 a = pv[lane & 15];
            unsigned long long s2 = fadd2(a.x, a.y);
            s2 = fadd2(s2, __shfl_xor_sync(0xffffffffu, s2, 1));
            s2 = fadd2(s2, __shfl_xor_sync(0xffffffffu, s2, 2));
            s2 = fadd2(s2, __shfl_xor_sync(0xffffffffu, s2, 4));
            s2 = fadd2(s2, __shfl_xor_sync(0xffffffffu, s2, 8));
            if (lane == 0) {
                float2 Sf = up2(s2);
                out[n0 + 2 * c]     = Cv[2 * c]     + logf(Sf.x);
                out[n0 + 2 * c + 1] = Cv[2 * c + 1] + logf(Sf.y);
            }
        }
    }
    cluster_sync_hw();                                // no early smem teardown
#undef PUSH_CHAIN
}

// ---------------- launch ------------------------------------------------------
extern "C" void kernel_launch(void* const* d_in, const int* in_sizes, int n_in,
                              void* d_out, int out_size) {
    const float* seq = nullptr;
    const int*   len = nullptr;
    const float* px  = nullptr;
    const float* py  = nullptr;
    for (int i = 0; i < n_in; i++) {
        switch (in_sizes[i]) {
            case Nn * Tn * Dn: seq = (const float*)d_in[i]; break;
            case Nn:           len = (const int*)d_in[i];   break;
            case Hn * Hn:      px  = (const float*)d_in[i]; break;
            case Hn * Dn:      py  = (const float*)d_in[i]; break;
        }
    }

    cudaFuncSetAttribute(hmm_k1, cudaFuncAttributeMaxDynamicSharedMemorySize, K1_SMEM);

    hmm_k0<<<64, 256>>>(py);
    hmm_k1<<<dim3(4, 512), 256, K1_SMEM>>>(seq);
    hmm_k2<<<4096, 256>>>();
    hmm_k3<<<16 * K3_CL, 256>>>(px, len, (float*)d_out);
}